// round 1
// baseline (speedup 1.0000x reference)
#include <cuda_runtime.h>
#include <cuda_bf16.h>
#include <math.h>

// Problem constants
#define S_LEN 2048
#define DIM   1536
#define NH    12
#define HD    128
#define CHALF (HD/2)            // 64
#define SEG0  (CHALF - 2*(CHALF/3))  // 22
#define SEG1  (CHALF/3)              // 21

// ---------------- scratch (device globals; no allocation allowed) ----------
__device__ float g_q[S_LEN * DIM];
__device__ float g_k[S_LEN * DIM];
__device__ float g_v[S_LEN * DIM];
__device__ float g_ao[S_LEN * DIM];

// ---------------- GEMM: C[M,N] = A[M,K] @ B[N,K]^T + bias[N] ---------------
// A row-major lda=K, B row-major ldb=K (NT gemm). M,N multiples of 128, K of 16.
#define BM 128
#define BN 128
#define BK 16

__global__ __launch_bounds__(256, 2)
void gemm_nt_bias(const float* __restrict__ A, const float* __restrict__ B,
                  const float* __restrict__ bias, float* __restrict__ C,
                  int M, int N, int K)
{
    __shared__ float As[BK][BM + 1];   // pitch 129 (odd) -> conflict-free stores
    __shared__ float Bs[BK][BN + 1];

    const int tid = threadIdx.x;
    const int ty  = tid >> 4;          // 0..15
    const int tx  = tid & 15;          // 0..15
    const int m0  = blockIdx.y * BM;
    const int n0  = blockIdx.x * BN;

    const int lrow = tid >> 2;         // 0..63
    const int lk4  = tid & 3;          // 0..3

    float acc[8][8];
#pragma unroll
    for (int i = 0; i < 8; i++)
#pragma unroll
        for (int j = 0; j < 8; j++) acc[i][j] = 0.f;

    for (int kb = 0; kb < K; kb += BK) {
#pragma unroll
        for (int half = 0; half < 2; half++) {
            int r = lrow + half * 64;
            float4 va = *(const float4*)(A + (size_t)(m0 + r) * K + kb + lk4 * 4);
            As[lk4*4+0][r] = va.x; As[lk4*4+1][r] = va.y;
            As[lk4*4+2][r] = va.z; As[lk4*4+3][r] = va.w;
            float4 vb = *(const float4*)(B + (size_t)(n0 + r) * K + kb + lk4 * 4);
            Bs[lk4*4+0][r] = vb.x; Bs[lk4*4+1][r] = vb.y;
            Bs[lk4*4+2][r] = vb.z; Bs[lk4*4+3][r] = vb.w;
        }
        __syncthreads();

#pragma unroll
        for (int kk = 0; kk < BK; kk++) {
            float a[8], b[8];
#pragma unroll
            for (int i = 0; i < 8; i++) a[i] = As[kk][ty * 8 + i];
#pragma unroll
            for (int j = 0; j < 8; j++) b[j] = Bs[kk][tx + 16 * j];   // stride-16 cols: conflict-free
#pragma unroll
            for (int i = 0; i < 8; i++)
#pragma unroll
                for (int j = 0; j < 8; j++) acc[i][j] = fmaf(a[i], b[j], acc[i][j]);
        }
        __syncthreads();
    }

#pragma unroll
    for (int j = 0; j < 8; j++) {
        int c = n0 + tx + 16 * j;
        float bv = bias[c];
#pragma unroll
        for (int i = 0; i < 8; i++) {
            C[(size_t)(m0 + ty * 8 + i) * N + c] = acc[i][j] + bv;
        }
    }
}

// ---------------- fused RMSNorm + RoPE on Q and K (in place) ---------------
__global__ __launch_bounds__(256)
void norm_rope_kernel(float* __restrict__ Q, float* __restrict__ K,
                      const float* __restrict__ gq, const float* __restrict__ gk,
                      const float* __restrict__ freqs, const int* __restrict__ grid_sizes)
{
    const int s   = blockIdx.x;
    const int tid = threadIdx.x;
    __shared__ float red[256];
    __shared__ float s_rq, s_rk;

    float* qrow = Q + (size_t)s * DIM;
    float* krow = K + (size_t)s * DIM;

    float sq = 0.f, sk = 0.f;
    for (int i = tid; i < DIM; i += 256) {
        float a = qrow[i]; sq += a * a;
        float b = krow[i]; sk += b * b;
    }
    // reduce sq
    red[tid] = sq; __syncthreads();
    for (int off = 128; off > 0; off >>= 1) {
        if (tid < off) red[tid] += red[tid + off];
        __syncthreads();
    }
    if (tid == 0) s_rq = rsqrtf(red[0] * (1.f / DIM) + 1e-6f);
    __syncthreads();
    // reduce sk
    red[tid] = sk; __syncthreads();
    for (int off = 128; off > 0; off >>= 1) {
        if (tid < off) red[tid] += red[tid + off];
        __syncthreads();
    }
    if (tid == 0) s_rk = rsqrtf(red[0] * (1.f / DIM) + 1e-6f);
    __syncthreads();

    const float rq = s_rq, rk = s_rk;

    const int fdim = grid_sizes[0];
    const int hdim = grid_sizes[1];
    const int wdim = grid_sizes[2];
    const int wi = s % wdim;
    const int hi = (s / wdim) % hdim;
    const int fi = s / (wdim * hdim);
    (void)fdim;

    for (int p = tid; p < NH * CHALF; p += 256) {
        const int head = p >> 6;        // CHALF == 64
        const int c    = p & 63;
        int pos = (c < SEG0) ? fi : ((c < SEG0 + SEG1) ? hi : wi);
        float ang = freqs[(size_t)pos * CHALF + c];
        float sn, cs;
        sincosf(ang, &sn, &cs);

        const int d0 = head * HD + 2 * c;
        float q0 = qrow[d0]     * rq * gq[d0];
        float q1 = qrow[d0 + 1] * rq * gq[d0 + 1];
        qrow[d0]     = q0 * cs - q1 * sn;
        qrow[d0 + 1] = q0 * sn + q1 * cs;

        float k0 = krow[d0]     * rk * gk[d0];
        float k1 = krow[d0 + 1] * rk * gk[d0 + 1];
        krow[d0]     = k0 * cs - k1 * sn;
        krow[d0 + 1] = k0 * sn + k1 * cs;
    }
}

// ---------------- flash attention, fp32 -------------------------------------
// grid: (S/64, NH), block 256 threads.
// smem: q[64][132], kT[128][68], v[64][132], s[64][68], m/l/alpha[64] each.
#define QT 64
#define QPITCH 132
#define KTPITCH 68
#define SPITCH 68

__global__ __launch_bounds__(256)
void flash_kernel(const float* __restrict__ Q, const float* __restrict__ K,
                  const float* __restrict__ V, float* __restrict__ O,
                  const int* __restrict__ seq_lens)
{
    extern __shared__ float sm[];
    float* q_s  = sm;                       // 64*132 = 8448
    float* kT_s = q_s  + QT * QPITCH;       // 128*68 = 8704
    float* v_s  = kT_s + HD * KTPITCH;      // 64*132 = 8448
    float* s_s  = v_s  + QT * QPITCH;       // 64*68  = 4352
    float* m_s  = s_s  + QT * SPITCH;       // 64
    float* l_s  = m_s  + QT;                // 64
    float* al_s = l_s  + QT;                // 64

    const int tid  = threadIdx.x;
    const int head = blockIdx.y;
    const int q0   = blockIdx.x * QT;
    const int seqlen = seq_lens[0];
    const float scale = 1.0f / sqrtf((float)HD);

    // load Q tile (coalesced float4)
    for (int idx = tid; idx < QT * (HD / 4); idx += 256) {
        int r = idx >> 5, d4 = idx & 31;
        float4 vq = *(const float4*)(Q + (size_t)(q0 + r) * DIM + head * HD + d4 * 4);
        *(float4*)(q_s + r * QPITCH + d4 * 4) = vq;
    }
    if (tid < QT) { m_s[tid] = -1e30f; l_s[tid] = 0.f; }

    // O accumulators: thread owns rows {pair*2, pair*2+1}, dims d = grp + 8*kk
    const int pair = tid >> 3;       // 0..31
    const int grp  = tid & 7;        // 0..7
    const int r0o  = pair * 2;
    float o_acc[32];
#pragma unroll
    for (int i = 0; i < 32; i++) o_acc[i] = 0.f;

    const int ty = tid >> 4, tx = tid & 15;   // score-phase mapping
    const int rr = tid >> 2, sub = tid & 3;   // softmax-phase mapping

    for (int kt = 0; kt < S_LEN / QT; kt++) {
        const int kr0 = kt * QT;
        __syncthreads();   // protect smem reuse (covers Q-tile/m/l init on iter 0)

        // load K transposed + V row-major
        for (int idx = tid; idx < QT * (HD / 4); idx += 256) {
            int r  = idx & 63, d4 = idx >> 6;
            float4 kv = *(const float4*)(K + (size_t)(kr0 + r) * DIM + head * HD + d4 * 4);
            kT_s[(d4*4+0) * KTPITCH + r] = kv.x;
            kT_s[(d4*4+1) * KTPITCH + r] = kv.y;
            kT_s[(d4*4+2) * KTPITCH + r] = kv.z;
            kT_s[(d4*4+3) * KTPITCH + r] = kv.w;
            int r2 = idx >> 5, dd4 = idx & 31;
            float4 vv = *(const float4*)(V + (size_t)(kr0 + r2) * DIM + head * HD + dd4 * 4);
            *(float4*)(v_s + r2 * QPITCH + dd4 * 4) = vv;
        }
        __syncthreads();

        // scores: rows ty*4+ii, cols tx+16*jj
        {
            float acc[4][4];
#pragma unroll
            for (int i = 0; i < 4; i++)
#pragma unroll
                for (int j = 0; j < 4; j++) acc[i][j] = 0.f;

#pragma unroll 4
            for (int d = 0; d < HD; d++) {
                float qa[4], kb[4];
#pragma unroll
                for (int ii = 0; ii < 4; ii++) qa[ii] = q_s[(ty * 4 + ii) * QPITCH + d];
#pragma unroll
                for (int jj = 0; jj < 4; jj++) kb[jj] = kT_s[d * KTPITCH + tx + 16 * jj];
#pragma unroll
                for (int ii = 0; ii < 4; ii++)
#pragma unroll
                    for (int jj = 0; jj < 4; jj++)
                        acc[ii][jj] = fmaf(qa[ii], kb[jj], acc[ii][jj]);
            }
#pragma unroll
            for (int ii = 0; ii < 4; ii++)
#pragma unroll
                for (int jj = 0; jj < 4; jj++) {
                    int col = kr0 + tx + 16 * jj;
                    float sv = acc[ii][jj] * scale;
                    if (col >= seqlen) sv = -1e30f;
                    s_s[(ty * 4 + ii) * SPITCH + tx + 16 * jj] = sv;
                }
        }
        __syncthreads();

        // online softmax: 4 threads per row, 16 cols each
        {
            float mx = -1e30f;
#pragma unroll
            for (int j = 0; j < 16; j++)
                mx = fmaxf(mx, s_s[rr * SPITCH + sub * 16 + j]);
            mx = fmaxf(mx, __shfl_xor_sync(0xffffffffu, mx, 1));
            mx = fmaxf(mx, __shfl_xor_sync(0xffffffffu, mx, 2));
            float m_old = m_s[rr];
            float m_new = fmaxf(m_old, mx);
            float sum = 0.f;
#pragma unroll
            for (int j = 0; j < 16; j++) {
                float p = __expf(s_s[rr * SPITCH + sub * 16 + j] - m_new);
                s_s[rr * SPITCH + sub * 16 + j] = p;
                sum += p;
            }
            sum += __shfl_xor_sync(0xffffffffu, sum, 1);
            sum += __shfl_xor_sync(0xffffffffu, sum, 2);
            if (sub == 0) {
                float alpha = __expf(m_old - m_new);
                m_s[rr]  = m_new;
                l_s[rr]  = l_s[rr] * alpha + sum;
                al_s[rr] = alpha;
            }
        }
        __syncthreads();

        // O update: o = o*alpha + P @ V
        {
            float a0 = al_s[r0o], a1 = al_s[r0o + 1];
#pragma unroll
            for (int kk = 0; kk < 16; kk++) { o_acc[kk] *= a0; o_acc[16 + kk] *= a1; }
            for (int j = 0; j < QT; j++) {
                float p0 = s_s[r0o * SPITCH + j];
                float p1 = s_s[(r0o + 1) * SPITCH + j];
#pragma unroll
                for (int kk = 0; kk < 16; kk++) {
                    float vv = v_s[j * QPITCH + grp + 8 * kk];
                    o_acc[kk]      = fmaf(p0, vv, o_acc[kk]);
                    o_acc[16 + kk] = fmaf(p1, vv, o_acc[16 + kk]);
                }
            }
        }
    }

    // normalize + write out
    {
        float inv0 = 1.f / l_s[r0o];
        float inv1 = 1.f / l_s[r0o + 1];
#pragma unroll
        for (int kk = 0; kk < 16; kk++) {
            O[(size_t)(q0 + r0o)     * DIM + head * HD + grp + 8 * kk] = o_acc[kk]      * inv0;
            O[(size_t)(q0 + r0o + 1) * DIM + head * HD + grp + 8 * kk] = o_acc[16 + kk] * inv1;
        }
    }
}

// ---------------- launcher ---------------------------------------------------
extern "C" void kernel_launch(void* const* d_in, const int* in_sizes, int n_in,
                              void* d_out, int out_size)
{
    const float* x     = (const float*)d_in[0];
    const float* freqs = (const float*)d_in[1];
    const float* wq    = (const float*)d_in[2];
    const float* bq    = (const float*)d_in[3];
    const float* wk    = (const float*)d_in[4];
    const float* bk    = (const float*)d_in[5];
    const float* wv    = (const float*)d_in[6];
    const float* bv    = (const float*)d_in[7];
    const float* wo    = (const float*)d_in[8];
    const float* bo    = (const float*)d_in[9];
    const float* gq    = (const float*)d_in[10];
    const float* gk    = (const float*)d_in[11];
    const int*   seq_lens   = (const int*)d_in[12];
    const int*   grid_sizes = (const int*)d_in[13];
    float* out = (float*)d_out;

    float *q, *k, *v, *ao;
    cudaGetSymbolAddress((void**)&q,  g_q);
    cudaGetSymbolAddress((void**)&k,  g_k);
    cudaGetSymbolAddress((void**)&v,  g_v);
    cudaGetSymbolAddress((void**)&ao, g_ao);

    dim3 gg(DIM / BN, S_LEN / BM);

    gemm_nt_bias<<<gg, 256>>>(x, wq, bq, q, S_LEN, DIM, DIM);
    gemm_nt_bias<<<gg, 256>>>(x, wk, bk, k, S_LEN, DIM, DIM);
    gemm_nt_bias<<<gg, 256>>>(x, wv, bv, v, S_LEN, DIM, DIM);

    norm_rope_kernel<<<S_LEN, 256>>>(q, k, gq, gk, freqs, grid_sizes);

    const int smem_bytes = (QT * QPITCH + HD * KTPITCH + QT * QPITCH +
                            QT * SPITCH + 3 * QT) * (int)sizeof(float);
    cudaFuncSetAttribute(flash_kernel, cudaFuncAttributeMaxDynamicSharedMemorySize, smem_bytes);
    flash_kernel<<<dim3(S_LEN / QT, NH), 256, smem_bytes>>>(q, k, v, ao, seq_lens);

    gemm_nt_bias<<<gg, 256>>>(ao, wo, bo, out, S_LEN, DIM, DIM);
}

// round 3
// speedup vs baseline: 1.6380x; 1.6380x over previous
#include <cuda_runtime.h>
#include <cuda_bf16.h>
#include <math.h>
#include <stdint.h>

// Problem constants
#define S_LEN 2048
#define DIM   1536
#define NH    12
#define HD    128
#define CHALF (HD/2)            // 64
#define SEG0  22
#define SEG1  21

// ---------------- scratch (device globals; no allocation allowed) ----------
__device__ float g_q[S_LEN * DIM];
__device__ float g_k[S_LEN * DIM];
__device__ float g_v[S_LEN * DIM];
__device__ float g_ao[S_LEN * DIM];

// bf16 split buffers (hi/lo), stored as uint4 (8 bf16 each)
__device__ uint4 g_xh[S_LEN * DIM / 8];
__device__ uint4 g_xl[S_LEN * DIM / 8];
__device__ uint4 g_wh[3 * DIM * DIM / 8];   // wq|wk|wv concatenated
__device__ uint4 g_wl[3 * DIM * DIM / 8];
__device__ uint4 g_oh[DIM * DIM / 8];       // wo
__device__ uint4 g_ol[DIM * DIM / 8];
__device__ uint4 g_aoh[S_LEN * DIM / 8];
__device__ uint4 g_aol[S_LEN * DIM / 8];

// ---------------- PTX helpers ------------------------------------------------
__device__ __forceinline__ uint32_t smem_u32(const void* p) {
    uint32_t a;
    asm("{ .reg .u64 t; cvta.to.shared.u64 t, %1; cvt.u32.u64 %0, t; }" : "=r"(a) : "l"(p));
    return a;
}
__device__ __forceinline__ void ldsm_x4(uint32_t* r, uint32_t addr) {
    asm volatile("ldmatrix.sync.aligned.m8n8.x4.shared.b16 {%0,%1,%2,%3}, [%4];"
        : "=r"(r[0]), "=r"(r[1]), "=r"(r[2]), "=r"(r[3]) : "r"(addr));
}
__device__ __forceinline__ void mma_bf16(float* c, const uint32_t* a, const uint32_t* b) {
    asm volatile(
        "mma.sync.aligned.m16n8k16.row.col.f32.bf16.bf16.f32 "
        "{%0,%1,%2,%3}, {%4,%5,%6,%7}, {%8,%9}, {%0,%1,%2,%3};"
        : "+f"(c[0]), "+f"(c[1]), "+f"(c[2]), "+f"(c[3])
        : "r"(a[0]), "r"(a[1]), "r"(a[2]), "r"(a[3]), "r"(b[0]), "r"(b[1]));
}
__device__ __forceinline__ void cp16(uint32_t dst, const void* src) {
    asm volatile("cp.async.cg.shared.global [%0], [%1], 16;" :: "r"(dst), "l"(src));
}
#define CP_COMMIT()  asm volatile("cp.async.commit_group;" ::: "memory")
#define CP_WAIT(n)   asm volatile("cp.async.wait_group %0;" :: "n"(n) : "memory")

// ---------------- fp32 -> bf16 hi/lo split conversion ------------------------
__global__ __launch_bounds__(256)
void conv_split(const float4* __restrict__ src, uint4* __restrict__ hi,
                uint4* __restrict__ lo, int n8)
{
    int idx = blockIdx.x * blockDim.x + threadIdx.x;
    if (idx >= n8) return;
    float4 a = src[2 * idx], b = src[2 * idx + 1];
    float xs[8] = {a.x, a.y, a.z, a.w, b.x, b.y, b.z, b.w};
    uint32_t h[4], l[4];
#pragma unroll
    for (int i = 0; i < 4; i++) {
        __nv_bfloat16 h0 = __float2bfloat16_rn(xs[2 * i]);
        __nv_bfloat16 h1 = __float2bfloat16_rn(xs[2 * i + 1]);
        float r0 = xs[2 * i]     - __bfloat162float(h0);
        float r1 = xs[2 * i + 1] - __bfloat162float(h1);
        __nv_bfloat16 l0 = __float2bfloat16_rn(r0);
        __nv_bfloat16 l1 = __float2bfloat16_rn(r1);
        h[i] = (uint32_t)__bfloat16_as_ushort(h0) | ((uint32_t)__bfloat16_as_ushort(h1) << 16);
        l[i] = (uint32_t)__bfloat16_as_ushort(l0) | ((uint32_t)__bfloat16_as_ushort(l1) << 16);
    }
    hi[idx] = make_uint4(h[0], h[1], h[2], h[3]);
    lo[idx] = make_uint4(l[0], l[1], l[2], l[3]);
}

// ---------------- bf16-split GEMM via mma.sync (HMMA) ------------------------
// CTA tile 128(m) x 128(n), BK=32, double-buffered cp.async.
// C[M, 1536-per-weight] = A[M,1536] @ W^T + bias, weights row-concatenated.
#define PITCH  80                 // bytes per smem row: 32 bf16 (64B) + 16B pad
#define TILEB  (128 * PITCH)      // 10240 B
#define STAGEB (4 * TILEB)        // Ah, Al, Bh, Bl
#define GEMM_SMEM (2 * STAGEB)    // 81920 B
#define NSTAGE 48                 // 1536 / 32

__global__ __launch_bounds__(256)
void gemm_mma(const uint4* __restrict__ Ah, const uint4* __restrict__ Al,
              const uint4* __restrict__ Wh, const uint4* __restrict__ Wl,
              const float* __restrict__ b0, const float* __restrict__ b1,
              const float* __restrict__ b2,
              float* __restrict__ C0, float* __restrict__ C1, float* __restrict__ C2,
              int ntw)
{
    extern __shared__ char smc[];
    const uint32_t sb = smem_u32(smc);
    const int tid  = threadIdx.x;
    const int wid  = tid >> 5;
    const int lane = tid & 31;
    const int warp_m = wid & 1;        // 0..1 -> 64 rows each
    const int warp_n = wid >> 1;       // 0..3 -> 32 cols each

    const int m0     = blockIdx.x * 128;
    const int ntile  = blockIdx.y;
    const int w      = ntile / ntw;
    const int ncol0  = (ntile % ntw) * 128;
    const size_t wrow0 = (size_t)ntile * 128;

    const int lr = tid >> 2;           // 0..63
    const int lj = tid & 3;            // uint4 within 32-bf16 row chunk

    float acc[4][4][4];
#pragma unroll
    for (int i = 0; i < 4; i++)
#pragma unroll
        for (int j = 0; j < 4; j++)
#pragma unroll
            for (int k = 0; k < 4; k++) acc[i][j][k] = 0.f;

    auto prefetch = [&](int c, int buf) {
        const uint32_t st = sb + buf * STAGEB;
        const int kc4 = c * 4;        // uint4 offset of this k-chunk within a row
#pragma unroll
        for (int i = 0; i < 2; i++) {
            int r = lr + i * 64;
            uint32_t so = (uint32_t)(r * PITCH + lj * 16);
            size_t ga = (size_t)(m0 + r) * (DIM / 8) + kc4 + lj;
            cp16(st + 0 * TILEB + so, Ah + ga);
            cp16(st + 1 * TILEB + so, Al + ga);
            size_t gb = (wrow0 + r) * (DIM / 8) + kc4 + lj;
            cp16(st + 2 * TILEB + so, Wh + gb);
            cp16(st + 3 * TILEB + so, Wl + gb);
        }
        CP_COMMIT();
    };

    prefetch(0, 0);
    prefetch(1, 1);

    // lane-dependent ldmatrix byte offsets
    const uint32_t a_lo = (uint32_t)((warp_m * 64 + (lane & 15)) * PITCH + (lane >> 4) * 16);
    const uint32_t b_lo = (uint32_t)((warp_n * 32 + (lane & 7) + ((lane >> 4) << 3)) * PITCH
                                     + ((lane >> 3) & 1) * 16);

    for (int c = 0; c < NSTAGE; c++) {
        if (c < NSTAGE - 1) { CP_WAIT(1); } else { CP_WAIT(0); }
        __syncthreads();

        const uint32_t st = sb + (c & 1) * STAGEB;
#pragma unroll
        for (int ks = 0; ks < 2; ks++) {
            uint32_t ah[4][4], al[4][4], bh[2][4], bl[2][4];
#pragma unroll
            for (int mt = 0; mt < 4; mt++) {
                uint32_t base = st + mt * (16 * PITCH) + ks * 32 + a_lo;
                ldsm_x4(ah[mt], base);
                ldsm_x4(al[mt], base + TILEB);
            }
#pragma unroll
            for (int np = 0; np < 2; np++) {
                uint32_t base = st + 2 * TILEB + np * (16 * PITCH) + ks * 32 + b_lo;
                ldsm_x4(bh[np], base);
                ldsm_x4(bl[np], base + TILEB);
            }
#pragma unroll
            for (int mt = 0; mt < 4; mt++) {
#pragma unroll
                for (int nt = 0; nt < 4; nt++) {
                    const uint32_t* bhp = &bh[nt >> 1][(nt & 1) * 2];
                    const uint32_t* blp = &bl[nt >> 1][(nt & 1) * 2];
                    mma_bf16(acc[mt][nt], ah[mt], bhp);
                    mma_bf16(acc[mt][nt], ah[mt], blp);
                    mma_bf16(acc[mt][nt], al[mt], bhp);
                }
            }
        }
        __syncthreads();
        if (c + 2 < NSTAGE) prefetch(c + 2, c & 1);
    }

    // epilogue
    float* C = (w == 0) ? C0 : (w == 1) ? C1 : C2;
    const float* bias = (w == 0) ? b0 : (w == 1) ? b1 : b2;
    const int g = lane >> 2, t4 = lane & 3;
#pragma unroll
    for (int mt = 0; mt < 4; mt++) {
        int row = m0 + warp_m * 64 + mt * 16 + g;
#pragma unroll
        for (int nt = 0; nt < 4; nt++) {
            int col = ncol0 + warp_n * 32 + nt * 8 + t4 * 2;
            float2 bv = *(const float2*)(bias + col);
            float2 o0, o1;
            o0.x = acc[mt][nt][0] + bv.x;  o0.y = acc[mt][nt][1] + bv.y;
            o1.x = acc[mt][nt][2] + bv.x;  o1.y = acc[mt][nt][3] + bv.y;
            *(float2*)(C + (size_t)row * DIM + col)       = o0;
            *(float2*)(C + (size_t)(row + 8) * DIM + col) = o1;
        }
    }
}

// ---------------- fused RMSNorm + RoPE on Q and K (in place) ---------------
__global__ __launch_bounds__(256)
void norm_rope_kernel(float* __restrict__ Q, float* __restrict__ K,
                      const float* __restrict__ gq, const float* __restrict__ gk,
                      const float* __restrict__ freqs, const int* __restrict__ grid_sizes)
{
    const int s   = blockIdx.x;
    const int tid = threadIdx.x;
    __shared__ float red[256];
    __shared__ float s_rq, s_rk;

    float* qrow = Q + (size_t)s * DIM;
    float* krow = K + (size_t)s * DIM;

    float sq = 0.f, sk = 0.f;
    for (int i = tid; i < DIM; i += 256) {
        float a = qrow[i]; sq += a * a;
        float b = krow[i]; sk += b * b;
    }
    red[tid] = sq; __syncthreads();
    for (int off = 128; off > 0; off >>= 1) {
        if (tid < off) red[tid] += red[tid + off];
        __syncthreads();
    }
    if (tid == 0) s_rq = rsqrtf(red[0] * (1.f / DIM) + 1e-6f);
    __syncthreads();
    red[tid] = sk; __syncthreads();
    for (int off = 128; off > 0; off >>= 1) {
        if (tid < off) red[tid] += red[tid + off];
        __syncthreads();
    }
    if (tid == 0) s_rk = rsqrtf(red[0] * (1.f / DIM) + 1e-6f);
    __syncthreads();

    const float rq = s_rq, rk = s_rk;

    const int hdim = grid_sizes[1];
    const int wdim = grid_sizes[2];
    const int wi = s % wdim;
    const int hi = (s / wdim) % hdim;
    const int fi = s / (wdim * hdim);

    for (int p = tid; p < NH * CHALF; p += 256) {
        const int head = p >> 6;
        const int c    = p & 63;
        int pos = (c < SEG0) ? fi : ((c < SEG0 + SEG1) ? hi : wi);
        float ang = freqs[(size_t)pos * CHALF + c];
        float sn, cs;
        sincosf(ang, &sn, &cs);

        const int d0 = head * HD + 2 * c;
        float q0 = qrow[d0]     * rq * gq[d0];
        float q1 = qrow[d0 + 1] * rq * gq[d0 + 1];
        qrow[d0]     = q0 * cs - q1 * sn;
        qrow[d0 + 1] = q0 * sn + q1 * cs;

        float k0 = krow[d0]     * rk * gk[d0];
        float k1 = krow[d0 + 1] * rk * gk[d0 + 1];
        krow[d0]     = k0 * cs - k1 * sn;
        krow[d0 + 1] = k0 * sn + k1 * cs;
    }
}

// ---------------- flash attention, fp32 (unchanged from R1) -----------------
#define QT 64
#define QPITCH 132
#define KTPITCH 68
#define SPITCH 68

__global__ __launch_bounds__(256)
void flash_kernel(const float* __restrict__ Q, const float* __restrict__ K,
                  const float* __restrict__ V, float* __restrict__ O,
                  const int* __restrict__ seq_lens)
{
    extern __shared__ float sm[];
    float* q_s  = sm;
    float* kT_s = q_s  + QT * QPITCH;
    float* v_s  = kT_s + HD * KTPITCH;
    float* s_s  = v_s  + QT * QPITCH;
    float* m_s  = s_s  + QT * SPITCH;
    float* l_s  = m_s  + QT;
    float* al_s = l_s  + QT;

    const int tid  = threadIdx.x;
    const int head = blockIdx.y;
    const int q0   = blockIdx.x * QT;
    const int seqlen = seq_lens[0];
    const float scale = 1.0f / sqrtf((float)HD);

    for (int idx = tid; idx < QT * (HD / 4); idx += 256) {
        int r = idx >> 5, d4 = idx & 31;
        float4 vq = *(const float4*)(Q + (size_t)(q0 + r) * DIM + head * HD + d4 * 4);
        *(float4*)(q_s + r * QPITCH + d4 * 4) = vq;
    }
    if (tid < QT) { m_s[tid] = -1e30f; l_s[tid] = 0.f; }

    const int pair = tid >> 3;
    const int grp  = tid & 7;
    const int r0o  = pair * 2;
    float o_acc[32];
#pragma unroll
    for (int i = 0; i < 32; i++) o_acc[i] = 0.f;

    const int ty = tid >> 4, tx = tid & 15;
    const int rr = tid >> 2, sub = tid & 3;

    for (int kt = 0; kt < S_LEN / QT; kt++) {
        const int kr0 = kt * QT;
        __syncthreads();

        for (int idx = tid; idx < QT * (HD / 4); idx += 256) {
            int r  = idx & 63, d4 = idx >> 6;
            float4 kv = *(const float4*)(K + (size_t)(kr0 + r) * DIM + head * HD + d4 * 4);
            kT_s[(d4*4+0) * KTPITCH + r] = kv.x;
            kT_s[(d4*4+1) * KTPITCH + r] = kv.y;
            kT_s[(d4*4+2) * KTPITCH + r] = kv.z;
            kT_s[(d4*4+3) * KTPITCH + r] = kv.w;
            int r2 = idx >> 5, dd4 = idx & 31;
            float4 vv = *(const float4*)(V + (size_t)(kr0 + r2) * DIM + head * HD + dd4 * 4);
            *(float4*)(v_s + r2 * QPITCH + dd4 * 4) = vv;
        }
        __syncthreads();

        {
            float acc[4][4];
#pragma unroll
            for (int i = 0; i < 4; i++)
#pragma unroll
                for (int j = 0; j < 4; j++) acc[i][j] = 0.f;

#pragma unroll 4
            for (int d = 0; d < HD; d++) {
                float qa[4], kb[4];
#pragma unroll
                for (int ii = 0; ii < 4; ii++) qa[ii] = q_s[(ty * 4 + ii) * QPITCH + d];
#pragma unroll
                for (int jj = 0; jj < 4; jj++) kb[jj] = kT_s[d * KTPITCH + tx + 16 * jj];
#pragma unroll
                for (int ii = 0; ii < 4; ii++)
#pragma unroll
                    for (int jj = 0; jj < 4; jj++)
                        acc[ii][jj] = fmaf(qa[ii], kb[jj], acc[ii][jj]);
            }
#pragma unroll
            for (int ii = 0; ii < 4; ii++)
#pragma unroll
                for (int jj = 0; jj < 4; jj++) {
                    int col = kr0 + tx + 16 * jj;
                    float sv = acc[ii][jj] * scale;
                    if (col >= seqlen) sv = -1e30f;
                    s_s[(ty * 4 + ii) * SPITCH + tx + 16 * jj] = sv;
                }
        }
        __syncthreads();

        {
            float mx = -1e30f;
#pragma unroll
            for (int j = 0; j < 16; j++)
                mx = fmaxf(mx, s_s[rr * SPITCH + sub * 16 + j]);
            mx = fmaxf(mx, __shfl_xor_sync(0xffffffffu, mx, 1));
            mx = fmaxf(mx, __shfl_xor_sync(0xffffffffu, mx, 2));
            float m_old = m_s[rr];
            float m_new = fmaxf(m_old, mx);
            float sum = 0.f;
#pragma unroll
            for (int j = 0; j < 16; j++) {
                float p = __expf(s_s[rr * SPITCH + sub * 16 + j] - m_new);
                s_s[rr * SPITCH + sub * 16 + j] = p;
                sum += p;
            }
            sum += __shfl_xor_sync(0xffffffffu, sum, 1);
            sum += __shfl_xor_sync(0xffffffffu, sum, 2);
            if (sub == 0) {
                float alpha = __expf(m_old - m_new);
                m_s[rr]  = m_new;
                l_s[rr]  = l_s[rr] * alpha + sum;
                al_s[rr] = alpha;
            }
        }
        __syncthreads();

        {
            float a0 = al_s[r0o], a1 = al_s[r0o + 1];
#pragma unroll
            for (int kk = 0; kk < 16; kk++) { o_acc[kk] *= a0; o_acc[16 + kk] *= a1; }
            for (int j = 0; j < QT; j++) {
                float p0 = s_s[r0o * SPITCH + j];
                float p1 = s_s[(r0o + 1) * SPITCH + j];
#pragma unroll
                for (int kk = 0; kk < 16; kk++) {
                    float vv = v_s[j * QPITCH + grp + 8 * kk];
                    o_acc[kk]      = fmaf(p0, vv, o_acc[kk]);
                    o_acc[16 + kk] = fmaf(p1, vv, o_acc[16 + kk]);
                }
            }
        }
    }

    {
        float inv0 = 1.f / l_s[r0o];
        float inv1 = 1.f / l_s[r0o + 1];
#pragma unroll
        for (int kk = 0; kk < 16; kk++) {
            O[(size_t)(q0 + r0o)     * DIM + head * HD + grp + 8 * kk] = o_acc[kk]      * inv0;
            O[(size_t)(q0 + r0o + 1) * DIM + head * HD + grp + 8 * kk] = o_acc[16 + kk] * inv1;
        }
    }
}

// ---------------- launcher ---------------------------------------------------
extern "C" void kernel_launch(void* const* d_in, const int* in_sizes, int n_in,
                              void* d_out, int out_size)
{
    const float* x     = (const float*)d_in[0];
    const float* freqs = (const float*)d_in[1];
    const float* wq    = (const float*)d_in[2];
    const float* bq    = (const float*)d_in[3];
    const float* wk    = (const float*)d_in[4];
    const float* bk    = (const float*)d_in[5];
    const float* wv    = (const float*)d_in[6];
    const float* bv    = (const float*)d_in[7];
    const float* wo    = (const float*)d_in[8];
    const float* bo    = (const float*)d_in[9];
    const float* gq    = (const float*)d_in[10];
    const float* gk    = (const float*)d_in[11];
    const int*   seq_lens   = (const int*)d_in[12];
    const int*   grid_sizes = (const int*)d_in[13];
    float* out = (float*)d_out;

    float *q, *k, *v, *ao;
    uint4 *xh, *xl, *wh, *wl, *oh, *ol, *aoh, *aol;
    cudaGetSymbolAddress((void**)&q,   g_q);
    cudaGetSymbolAddress((void**)&k,   g_k);
    cudaGetSymbolAddress((void**)&v,   g_v);
    cudaGetSymbolAddress((void**)&ao,  g_ao);
    cudaGetSymbolAddress((void**)&xh,  g_xh);
    cudaGetSymbolAddress((void**)&xl,  g_xl);
    cudaGetSymbolAddress((void**)&wh,  g_wh);
    cudaGetSymbolAddress((void**)&wl,  g_wl);
    cudaGetSymbolAddress((void**)&oh,  g_oh);
    cudaGetSymbolAddress((void**)&ol,  g_ol);
    cudaGetSymbolAddress((void**)&aoh, g_aoh);
    cudaGetSymbolAddress((void**)&aol, g_aol);

    const int n8x = S_LEN * DIM / 8;
    const int n8w = DIM * DIM / 8;

    conv_split<<<(n8x + 255) / 256, 256>>>((const float4*)x, xh, xl, n8x);
    conv_split<<<(n8w + 255) / 256, 256>>>((const float4*)wq, wh, wl, n8w);
    conv_split<<<(n8w + 255) / 256, 256>>>((const float4*)wk, wh + n8w, wl + n8w, n8w);
    conv_split<<<(n8w + 255) / 256, 256>>>((const float4*)wv, wh + 2 * n8w, wl + 2 * n8w, n8w);
    conv_split<<<(n8w + 255) / 256, 256>>>((const float4*)wo, oh, ol, n8w);

    cudaFuncSetAttribute(gemm_mma, cudaFuncAttributeMaxDynamicSharedMemorySize, GEMM_SMEM);

    // fused QKV: 36 n-tiles of 128 over concatenated [wq|wk|wv]
    gemm_mma<<<dim3(S_LEN / 128, 36), 256, GEMM_SMEM>>>(
        xh, xl, wh, wl, bq, bk, bv, q, k, v, DIM / 128);

    norm_rope_kernel<<<S_LEN, 256>>>(q, k, gq, gk, freqs, grid_sizes);

    const int fl_smem = (QT * QPITCH + HD * KTPITCH + QT * QPITCH +
                         QT * SPITCH + 3 * QT) * (int)sizeof(float);
    cudaFuncSetAttribute(flash_kernel, cudaFuncAttributeMaxDynamicSharedMemorySize, fl_smem);
    flash_kernel<<<dim3(S_LEN / QT, NH), 256, fl_smem>>>(q, k, v, ao, seq_lens);

    conv_split<<<(n8x + 255) / 256, 256>>>((const float4*)ao, aoh, aol, n8x);

    // output projection: 12 n-tiles of 128
    gemm_mma<<<dim3(S_LEN / 128, 12), 256, GEMM_SMEM>>>(
        aoh, aol, oh, ol, bo, bo, bo, out, out, out, DIM / 128);
}

// round 4
// speedup vs baseline: 3.7721x; 2.3028x over previous
#include <cuda_runtime.h>
#include <cuda_bf16.h>
#include <math.h>
#include <stdint.h>

// Problem constants
#define S_LEN 2048
#define DIM   1536
#define NH    12
#define HD    128
#define CHALF (HD/2)
#define SEG0  22
#define SEG1  21

// ---------------- scratch (device globals) ----------------------------------
__device__ float g_q[S_LEN * DIM];
__device__ float g_k[S_LEN * DIM];
__device__ float g_v[S_LEN * DIM];
__device__ float g_ao[S_LEN * DIM];

__device__ uint4 g_xh[S_LEN * DIM / 8];     // x split; reused for Q split
__device__ uint4 g_xl[S_LEN * DIM / 8];
__device__ uint4 g_wh[3 * DIM * DIM / 8];   // wq|wk|wv split; reused for V split hi
__device__ uint4 g_wl[3 * DIM * DIM / 8];   // reused for V split lo
__device__ uint4 g_oh[DIM * DIM / 8];       // wo split
__device__ uint4 g_ol[DIM * DIM / 8];
__device__ uint4 g_aoh[S_LEN * DIM / 8];    // K split; reused for ao split
__device__ uint4 g_aol[S_LEN * DIM / 8];

// ---------------- PTX helpers ------------------------------------------------
__device__ __forceinline__ uint32_t smem_u32(const void* p) {
    uint32_t a;
    asm("{ .reg .u64 t; cvta.to.shared.u64 t, %1; cvt.u32.u64 %0, t; }" : "=r"(a) : "l"(p));
    return a;
}
__device__ __forceinline__ void ldsm_x4(uint32_t* r, uint32_t addr) {
    asm volatile("ldmatrix.sync.aligned.m8n8.x4.shared.b16 {%0,%1,%2,%3}, [%4];"
        : "=r"(r[0]), "=r"(r[1]), "=r"(r[2]), "=r"(r[3]) : "r"(addr));
}
__device__ __forceinline__ void ldsm_x4_t(uint32_t* r, uint32_t addr) {
    asm volatile("ldmatrix.sync.aligned.m8n8.x4.trans.shared.b16 {%0,%1,%2,%3}, [%4];"
        : "=r"(r[0]), "=r"(r[1]), "=r"(r[2]), "=r"(r[3]) : "r"(addr));
}
__device__ __forceinline__ void mma_bf16(float* c, const uint32_t* a, const uint32_t* b) {
    asm volatile(
        "mma.sync.aligned.m16n8k16.row.col.f32.bf16.bf16.f32 "
        "{%0,%1,%2,%3}, {%4,%5,%6,%7}, {%8,%9}, {%0,%1,%2,%3};"
        : "+f"(c[0]), "+f"(c[1]), "+f"(c[2]), "+f"(c[3])
        : "r"(a[0]), "r"(a[1]), "r"(a[2]), "r"(a[3]), "r"(b[0]), "r"(b[1]));
}
__device__ __forceinline__ void cp16(uint32_t dst, const void* src) {
    asm volatile("cp.async.cg.shared.global [%0], [%1], 16;" :: "r"(dst), "l"(src));
}
#define CP_COMMIT()  asm volatile("cp.async.commit_group;" ::: "memory")
#define CP_WAIT(n)   asm volatile("cp.async.wait_group %0;" :: "n"(n) : "memory")

__device__ __forceinline__ uint32_t pack2(float lo, float hi) {
    __nv_bfloat16 a = __float2bfloat16_rn(lo);
    __nv_bfloat16 b = __float2bfloat16_rn(hi);
    return (uint32_t)__bfloat16_as_ushort(a) | ((uint32_t)__bfloat16_as_ushort(b) << 16);
}

// ---------------- fp32 -> bf16 hi/lo split (optional pre-scale) --------------
__global__ __launch_bounds__(256)
void conv_split(const float4* __restrict__ src, uint4* __restrict__ hi,
                uint4* __restrict__ lo, int n8, float scale)
{
    int idx = blockIdx.x * blockDim.x + threadIdx.x;
    if (idx >= n8) return;
    float4 a = src[2 * idx], b = src[2 * idx + 1];
    float xs[8] = {a.x, a.y, a.z, a.w, b.x, b.y, b.z, b.w};
    uint32_t h[4], l[4];
#pragma unroll
    for (int i = 0; i < 4; i++) {
        float v0 = xs[2 * i] * scale, v1 = xs[2 * i + 1] * scale;
        __nv_bfloat16 h0 = __float2bfloat16_rn(v0);
        __nv_bfloat16 h1 = __float2bfloat16_rn(v1);
        float r0 = v0 - __bfloat162float(h0);
        float r1 = v1 - __bfloat162float(h1);
        __nv_bfloat16 l0 = __float2bfloat16_rn(r0);
        __nv_bfloat16 l1 = __float2bfloat16_rn(r1);
        h[i] = (uint32_t)__bfloat16_as_ushort(h0) | ((uint32_t)__bfloat16_as_ushort(h1) << 16);
        l[i] = (uint32_t)__bfloat16_as_ushort(l0) | ((uint32_t)__bfloat16_as_ushort(l1) << 16);
    }
    hi[idx] = make_uint4(h[0], h[1], h[2], h[3]);
    lo[idx] = make_uint4(l[0], l[1], l[2], l[3]);
}

// ---------------- bf16-split GEMM via mma.sync (from R3, unchanged) ----------
#define PITCH  80
#define TILEB  (128 * PITCH)
#define STAGEB (4 * TILEB)
#define GEMM_SMEM (2 * STAGEB)
#define NSTAGE 48

__global__ __launch_bounds__(256)
void gemm_mma(const uint4* __restrict__ Ah, const uint4* __restrict__ Al,
              const uint4* __restrict__ Wh, const uint4* __restrict__ Wl,
              const float* __restrict__ b0, const float* __restrict__ b1,
              const float* __restrict__ b2,
              float* __restrict__ C0, float* __restrict__ C1, float* __restrict__ C2,
              int ntw)
{
    extern __shared__ char smc[];
    const uint32_t sb = smem_u32(smc);
    const int tid  = threadIdx.x;
    const int wid  = tid >> 5;
    const int lane = tid & 31;
    const int warp_m = wid & 1;
    const int warp_n = wid >> 1;

    const int m0     = blockIdx.x * 128;
    const int ntile  = blockIdx.y;
    const int w      = ntile / ntw;
    const int ncol0  = (ntile % ntw) * 128;
    const size_t wrow0 = (size_t)ntile * 128;

    const int lr = tid >> 2;
    const int lj = tid & 3;

    float acc[4][4][4];
#pragma unroll
    for (int i = 0; i < 4; i++)
#pragma unroll
        for (int j = 0; j < 4; j++)
#pragma unroll
            for (int k = 0; k < 4; k++) acc[i][j][k] = 0.f;

    auto prefetch = [&](int c, int buf) {
        const uint32_t st = sb + buf * STAGEB;
        const int kc4 = c * 4;
#pragma unroll
        for (int i = 0; i < 2; i++) {
            int r = lr + i * 64;
            uint32_t so = (uint32_t)(r * PITCH + lj * 16);
            size_t ga = (size_t)(m0 + r) * (DIM / 8) + kc4 + lj;
            cp16(st + 0 * TILEB + so, Ah + ga);
            cp16(st + 1 * TILEB + so, Al + ga);
            size_t gb = (wrow0 + r) * (DIM / 8) + kc4 + lj;
            cp16(st + 2 * TILEB + so, Wh + gb);
            cp16(st + 3 * TILEB + so, Wl + gb);
        }
        CP_COMMIT();
    };

    prefetch(0, 0);
    prefetch(1, 1);

    const uint32_t a_lo = (uint32_t)((warp_m * 64 + (lane & 15)) * PITCH + (lane >> 4) * 16);
    const uint32_t b_lo = (uint32_t)((warp_n * 32 + (lane & 7) + ((lane >> 4) << 3)) * PITCH
                                     + ((lane >> 3) & 1) * 16);

    for (int c = 0; c < NSTAGE; c++) {
        if (c < NSTAGE - 1) { CP_WAIT(1); } else { CP_WAIT(0); }
        __syncthreads();

        const uint32_t st = sb + (c & 1) * STAGEB;
#pragma unroll
        for (int ks = 0; ks < 2; ks++) {
            uint32_t ah[4][4], al[4][4], bh[2][4], bl[2][4];
#pragma unroll
            for (int mt = 0; mt < 4; mt++) {
                uint32_t base = st + mt * (16 * PITCH) + ks * 32 + a_lo;
                ldsm_x4(ah[mt], base);
                ldsm_x4(al[mt], base + TILEB);
            }
#pragma unroll
            for (int np = 0; np < 2; np++) {
                uint32_t base = st + 2 * TILEB + np * (16 * PITCH) + ks * 32 + b_lo;
                ldsm_x4(bh[np], base);
                ldsm_x4(bl[np], base + TILEB);
            }
#pragma unroll
            for (int mt = 0; mt < 4; mt++) {
#pragma unroll
                for (int nt = 0; nt < 4; nt++) {
                    const uint32_t* bhp = &bh[nt >> 1][(nt & 1) * 2];
                    const uint32_t* blp = &bl[nt >> 1][(nt & 1) * 2];
                    mma_bf16(acc[mt][nt], ah[mt], bhp);
                    mma_bf16(acc[mt][nt], ah[mt], blp);
                    mma_bf16(acc[mt][nt], al[mt], bhp);
                }
            }
        }
        __syncthreads();
        if (c + 2 < NSTAGE) prefetch(c + 2, c & 1);
    }

    float* C = (w == 0) ? C0 : (w == 1) ? C1 : C2;
    const float* bias = (w == 0) ? b0 : (w == 1) ? b1 : b2;
    const int g = lane >> 2, t4 = lane & 3;
#pragma unroll
    for (int mt = 0; mt < 4; mt++) {
        int row = m0 + warp_m * 64 + mt * 16 + g;
#pragma unroll
        for (int nt = 0; nt < 4; nt++) {
            int col = ncol0 + warp_n * 32 + nt * 8 + t4 * 2;
            float2 bv = *(const float2*)(bias + col);
            float2 o0, o1;
            o0.x = acc[mt][nt][0] + bv.x;  o0.y = acc[mt][nt][1] + bv.y;
            o1.x = acc[mt][nt][2] + bv.x;  o1.y = acc[mt][nt][3] + bv.y;
            *(float2*)(C + (size_t)row * DIM + col)       = o0;
            *(float2*)(C + (size_t)(row + 8) * DIM + col) = o1;
        }
    }
}

// ---------------- fused RMSNorm + RoPE on Q and K (in place) ---------------
__global__ __launch_bounds__(256)
void norm_rope_kernel(float* __restrict__ Q, float* __restrict__ K,
                      const float* __restrict__ gq, const float* __restrict__ gk,
                      const float* __restrict__ freqs, const int* __restrict__ grid_sizes)
{
    const int s   = blockIdx.x;
    const int tid = threadIdx.x;
    __shared__ float red[256];
    __shared__ float s_rq, s_rk;

    float* qrow = Q + (size_t)s * DIM;
    float* krow = K + (size_t)s * DIM;

    float sq = 0.f, sk = 0.f;
    for (int i = tid; i < DIM; i += 256) {
        float a = qrow[i]; sq += a * a;
        float b = krow[i]; sk += b * b;
    }
    red[tid] = sq; __syncthreads();
    for (int off = 128; off > 0; off >>= 1) {
        if (tid < off) red[tid] += red[tid + off];
        __syncthreads();
    }
    if (tid == 0) s_rq = rsqrtf(red[0] * (1.f / DIM) + 1e-6f);
    __syncthreads();
    red[tid] = sk; __syncthreads();
    for (int off = 128; off > 0; off >>= 1) {
        if (tid < off) red[tid] += red[tid + off];
        __syncthreads();
    }
    if (tid == 0) s_rk = rsqrtf(red[0] * (1.f / DIM) + 1e-6f);
    __syncthreads();

    const float rq = s_rq, rk = s_rk;

    const int hdim = grid_sizes[1];
    const int wdim = grid_sizes[2];
    const int wi = s % wdim;
    const int hi = (s / wdim) % hdim;
    const int fi = s / (wdim * hdim);

    for (int p = tid; p < NH * CHALF; p += 256) {
        const int head = p >> 6;
        const int c    = p & 63;
        int pos = (c < SEG0) ? fi : ((c < SEG0 + SEG1) ? hi : wi);
        float ang = freqs[(size_t)pos * CHALF + c];
        float sn, cs;
        sincosf(ang, &sn, &cs);

        const int d0 = head * HD + 2 * c;
        float q0 = qrow[d0]     * rq * gq[d0];
        float q1 = qrow[d0 + 1] * rq * gq[d0 + 1];
        qrow[d0]     = q0 * cs - q1 * sn;
        qrow[d0 + 1] = q0 * sn + q1 * cs;

        float k0 = krow[d0]     * rk * gk[d0];
        float k1 = krow[d0 + 1] * rk * gk[d0 + 1];
        krow[d0]     = k0 * cs - k1 * sn;
        krow[d0 + 1] = k0 * sn + k1 * cs;
    }
}

// ---------------- flash attention via mma.sync bf16-split --------------------
// grid (S/128, NH), block 256 (8 warps x 16 q-rows). KV tiles of 64 keys,
// double-buffered cp.async. Q pre-scaled by 1/sqrt(HD) at split time.
#define FQT    128
#define FKT    64
#define FPITCH 272                      // bytes per 128-bf16 row (17x16B: swizzle-free)
#define QH_OFF 0
#define QL_OFF (128 * FPITCH)           // 34816
#define STG_OFF (2 * 128 * FPITCH)      // 69632
#define KH_O   0
#define KL_O   (64 * FPITCH)            // 17408
#define VH_O   (2 * 64 * FPITCH)        // 34816
#define VL_O   (3 * 64 * FPITCH)        // 52224
#define STG_SZ (4 * 64 * FPITCH)        // 69632
#define FL_SMEM (STG_OFF + 2 * STG_SZ)  // 208896

__global__ __launch_bounds__(256, 1)
void flash_mma(const uint4* __restrict__ Qh, const uint4* __restrict__ Ql,
               const uint4* __restrict__ Kh, const uint4* __restrict__ Kl,
               const uint4* __restrict__ Vh, const uint4* __restrict__ Vl,
               float* __restrict__ O, const int* __restrict__ seq_lens)
{
    extern __shared__ char smc[];
    const uint32_t sb = smem_u32(smc);
    const int tid  = threadIdx.x;
    const int wid  = tid >> 5;
    const int lane = tid & 31;
    const int g    = lane >> 2;
    const int t4   = lane & 3;
    const int head = blockIdx.y;
    const int q0   = blockIdx.x * FQT;
    const int seqlen = seq_lens[0];

    const int DIM8 = DIM / 8;       // 192 uint4 per row
    const int h8   = head * (HD / 8);

    // Q tiles (hi/lo) via cp.async, loaded once
#pragma unroll
    for (int i = 0; i < 8; i++) {
        int t = tid + 256 * i;      // 0..2047
        int r = t >> 4, j = t & 15;
        uint32_t so = (uint32_t)(r * FPITCH + j * 16);
        size_t gi = (size_t)(q0 + r) * DIM8 + h8 + j;
        cp16(sb + QH_OFF + so, Qh + gi);
        cp16(sb + QL_OFF + so, Ql + gi);
    }
    CP_COMMIT();

    auto load_kv = [&](int kt, int buf) {
        uint32_t st = sb + STG_OFF + buf * STG_SZ;
        int kr0 = kt * FKT;
#pragma unroll
        for (int i = 0; i < 4; i++) {
            int t = tid + 256 * i;  // 0..1023
            int r = t >> 4, j = t & 15;
            uint32_t so = (uint32_t)(r * FPITCH + j * 16);
            size_t gi = (size_t)(kr0 + r) * DIM8 + h8 + j;
            cp16(st + KH_O + so, Kh + gi);
            cp16(st + KL_O + so, Kl + gi);
            cp16(st + VH_O + so, Vh + gi);
            cp16(st + VL_O + so, Vl + gi);
        }
        CP_COMMIT();
    };

    load_kv(0, 0);
    load_kv(1, 1);

    float o[16][4];
#pragma unroll
    for (int i = 0; i < 16; i++)
#pragma unroll
        for (int j = 0; j < 4; j++) o[i][j] = 0.f;
    float m0 = -1e30f, m1 = -1e30f, l0 = 0.f, l1 = 0.f;

    const uint32_t a_off  = (uint32_t)((wid * 16 + (lane & 15)) * FPITCH + (lane >> 4) * 16);
    const uint32_t bk_off = (uint32_t)(((lane & 7) + ((lane >> 4) << 3)) * FPITCH
                                       + ((lane >> 3) & 1) * 16);
    const uint32_t bv_row = (uint32_t)((lane & 7) + (((lane >> 3) & 1) << 3));
    const uint32_t bv_col = (uint32_t)((lane >> 4) * 16);

    const int NT = S_LEN / FKT;     // 32
    for (int kt = 0; kt < NT; kt++) {
        if (kt < NT - 1) { CP_WAIT(1); } else { CP_WAIT(0); }
        __syncthreads();
        const uint32_t st = sb + STG_OFF + (kt & 1) * STG_SZ;

        // ---- scores: 128x64, 3-term split ----
        float acc[8][4];
#pragma unroll
        for (int i = 0; i < 8; i++)
#pragma unroll
            for (int j = 0; j < 4; j++) acc[i][j] = 0.f;

#pragma unroll
        for (int kk = 0; kk < 8; kk++) {
            uint32_t aqh[4], aql[4];
            ldsm_x4(aqh, sb + QH_OFF + a_off + kk * 32);
            ldsm_x4(aql, sb + QL_OFF + a_off + kk * 32);
#pragma unroll
            for (int np = 0; np < 4; np++) {
                uint32_t bh[4], bl[4];
                uint32_t kb = st + np * (16 * FPITCH) + bk_off + kk * 32;
                ldsm_x4(bh, kb + KH_O);
                ldsm_x4(bl, kb + KL_O);
                mma_bf16(acc[2*np],   aqh, &bh[0]);
                mma_bf16(acc[2*np+1], aqh, &bh[2]);
                mma_bf16(acc[2*np],   aqh, &bl[0]);
                mma_bf16(acc[2*np+1], aqh, &bl[2]);
                mma_bf16(acc[2*np],   aql, &bh[0]);
                mma_bf16(acc[2*np+1], aql, &bh[2]);
            }
        }

        // ---- mask + online softmax (register fragments) ----
        const int kr0 = kt * FKT;
        float mx0 = -1e30f, mx1 = -1e30f;
#pragma unroll
        for (int j = 0; j < 8; j++) {
            int c0 = kr0 + 8 * j + 2 * t4;
            if (c0 >= seqlen)     { acc[j][0] = -1e30f; acc[j][2] = -1e30f; }
            if (c0 + 1 >= seqlen) { acc[j][1] = -1e30f; acc[j][3] = -1e30f; }
            mx0 = fmaxf(mx0, fmaxf(acc[j][0], acc[j][1]));
            mx1 = fmaxf(mx1, fmaxf(acc[j][2], acc[j][3]));
        }
        mx0 = fmaxf(mx0, __shfl_xor_sync(0xffffffffu, mx0, 1));
        mx0 = fmaxf(mx0, __shfl_xor_sync(0xffffffffu, mx0, 2));
        mx1 = fmaxf(mx1, __shfl_xor_sync(0xffffffffu, mx1, 1));
        mx1 = fmaxf(mx1, __shfl_xor_sync(0xffffffffu, mx1, 2));

        float mn0 = fmaxf(m0, mx0), mn1 = fmaxf(m1, mx1);
        float al0 = __expf(m0 - mn0), al1 = __expf(m1 - mn1);
        m0 = mn0; m1 = mn1;

        float s0 = 0.f, s1 = 0.f;
        uint32_t ph0[8], ph1[8], pl0[8], pl1[8];
#pragma unroll
        for (int j = 0; j < 8; j++) {
            float p00 = __expf(acc[j][0] - mn0);
            float p01 = __expf(acc[j][1] - mn0);
            float p10 = __expf(acc[j][2] - mn1);
            float p11 = __expf(acc[j][3] - mn1);
            s0 += p00 + p01;
            s1 += p10 + p11;
            // split P: hi + residual
            __nv_bfloat16 h00 = __float2bfloat16_rn(p00);
            __nv_bfloat16 h01 = __float2bfloat16_rn(p01);
            __nv_bfloat16 h10 = __float2bfloat16_rn(p10);
            __nv_bfloat16 h11 = __float2bfloat16_rn(p11);
            ph0[j] = (uint32_t)__bfloat16_as_ushort(h00) | ((uint32_t)__bfloat16_as_ushort(h01) << 16);
            ph1[j] = (uint32_t)__bfloat16_as_ushort(h10) | ((uint32_t)__bfloat16_as_ushort(h11) << 16);
            pl0[j] = pack2(p00 - __bfloat162float(h00), p01 - __bfloat162float(h01));
            pl1[j] = pack2(p10 - __bfloat162float(h10), p11 - __bfloat162float(h11));
        }
        s0 += __shfl_xor_sync(0xffffffffu, s0, 1);
        s0 += __shfl_xor_sync(0xffffffffu, s0, 2);
        s1 += __shfl_xor_sync(0xffffffffu, s1, 1);
        s1 += __shfl_xor_sync(0xffffffffu, s1, 2);
        l0 = l0 * al0 + s0;
        l1 = l1 * al1 + s1;

#pragma unroll
        for (int nt = 0; nt < 16; nt++) {
            o[nt][0] *= al0; o[nt][1] *= al0;
            o[nt][2] *= al1; o[nt][3] *= al1;
        }

        // ---- PV: P(128x64) @ V(64x128), 3-term split ----
#pragma unroll
        for (int k2 = 0; k2 < 4; k2++) {
            uint32_t aph[4] = { ph0[2*k2], ph1[2*k2], ph0[2*k2+1], ph1[2*k2+1] };
            uint32_t apl[4] = { pl0[2*k2], pl1[2*k2], pl0[2*k2+1], pl1[2*k2+1] };
            uint32_t vrow = st + (uint32_t)((k2 * 16 + bv_row) * FPITCH) + bv_col;
#pragma unroll
            for (int d = 0; d < 8; d++) {
                uint32_t bvh[4], bvl[4];
                ldsm_x4_t(bvh, vrow + VH_O + d * 32);
                ldsm_x4_t(bvl, vrow + VL_O + d * 32);
                mma_bf16(o[2*d],   aph, &bvh[0]);
                mma_bf16(o[2*d+1], aph, &bvh[2]);
                mma_bf16(o[2*d],   aph, &bvl[0]);
                mma_bf16(o[2*d+1], aph, &bvl[2]);
                mma_bf16(o[2*d],   apl, &bvh[0]);
                mma_bf16(o[2*d+1], apl, &bvh[2]);
            }
        }
        __syncthreads();
        if (kt + 2 < NT) load_kv(kt + 2, kt & 1);
    }

    // ---- epilogue ----
    float i0 = 1.f / l0, i1 = 1.f / l1;
    const int row0 = q0 + wid * 16 + g;
#pragma unroll
    for (int nt = 0; nt < 16; nt++) {
        int col = head * HD + nt * 8 + 2 * t4;
        float2 v0, v1;
        v0.x = o[nt][0] * i0; v0.y = o[nt][1] * i0;
        v1.x = o[nt][2] * i1; v1.y = o[nt][3] * i1;
        *(float2*)(O + (size_t)row0 * DIM + col)       = v0;
        *(float2*)(O + (size_t)(row0 + 8) * DIM + col) = v1;
    }
}

// ---------------- launcher ---------------------------------------------------
extern "C" void kernel_launch(void* const* d_in, const int* in_sizes, int n_in,
                              void* d_out, int out_size)
{
    const float* x     = (const float*)d_in[0];
    const float* freqs = (const float*)d_in[1];
    const float* wq    = (const float*)d_in[2];
    const float* bq    = (const float*)d_in[3];
    const float* wk    = (const float*)d_in[4];
    const float* bk    = (const float*)d_in[5];
    const float* wv    = (const float*)d_in[6];
    const float* bv    = (const float*)d_in[7];
    const float* wo    = (const float*)d_in[8];
    const float* bo    = (const float*)d_in[9];
    const float* gq    = (const float*)d_in[10];
    const float* gk    = (const float*)d_in[11];
    const int*   seq_lens   = (const int*)d_in[12];
    const int*   grid_sizes = (const int*)d_in[13];
    float* out = (float*)d_out;

    float *q, *k, *v, *ao;
    uint4 *xh, *xl, *wh, *wl, *oh, *ol, *aoh, *aol;
    cudaGetSymbolAddress((void**)&q,   g_q);
    cudaGetSymbolAddress((void**)&k,   g_k);
    cudaGetSymbolAddress((void**)&v,   g_v);
    cudaGetSymbolAddress((void**)&ao,  g_ao);
    cudaGetSymbolAddress((void**)&xh,  g_xh);
    cudaGetSymbolAddress((void**)&xl,  g_xl);
    cudaGetSymbolAddress((void**)&wh,  g_wh);
    cudaGetSymbolAddress((void**)&wl,  g_wl);
    cudaGetSymbolAddress((void**)&oh,  g_oh);
    cudaGetSymbolAddress((void**)&ol,  g_ol);
    cudaGetSymbolAddress((void**)&aoh, g_aoh);
    cudaGetSymbolAddress((void**)&aol, g_aol);

    const int n8x = S_LEN * DIM / 8;
    const int n8w = DIM * DIM / 8;
    const float qscale = 1.0f / sqrtf((float)HD);

    conv_split<<<(n8x + 255) / 256, 256>>>((const float4*)x, xh, xl, n8x, 1.f);
    conv_split<<<(n8w + 255) / 256, 256>>>((const float4*)wq, wh, wl, n8w, 1.f);
    conv_split<<<(n8w + 255) / 256, 256>>>((const float4*)wk, wh + n8w, wl + n8w, n8w, 1.f);
    conv_split<<<(n8w + 255) / 256, 256>>>((const float4*)wv, wh + 2 * n8w, wl + 2 * n8w, n8w, 1.f);
    conv_split<<<(n8w + 255) / 256, 256>>>((const float4*)wo, oh, ol, n8w, 1.f);

    cudaFuncSetAttribute(gemm_mma, cudaFuncAttributeMaxDynamicSharedMemorySize, GEMM_SMEM);

    // fused QKV
    gemm_mma<<<dim3(S_LEN / 128, 36), 256, GEMM_SMEM>>>(
        xh, xl, wh, wl, bq, bk, bv, q, k, v, DIM / 128);

    norm_rope_kernel<<<S_LEN, 256>>>(q, k, gq, gk, freqs, grid_sizes);

    // splits for attention: Q (pre-scaled), K, V.  x/w splits are dead now.
    conv_split<<<(n8x + 255) / 256, 256>>>((const float4*)q, xh, xl, n8x, qscale);
    conv_split<<<(n8x + 255) / 256, 256>>>((const float4*)k, aoh, aol, n8x, 1.f);
    conv_split<<<(n8x + 255) / 256, 256>>>((const float4*)v, wh, wl, n8x, 1.f);

    cudaFuncSetAttribute(flash_mma, cudaFuncAttributeMaxDynamicSharedMemorySize, FL_SMEM);
    flash_mma<<<dim3(S_LEN / FQT, NH), 256, FL_SMEM>>>(
        xh, xl, aoh, aol, wh, wl, ao, seq_lens);

    conv_split<<<(n8x + 255) / 256, 256>>>((const float4*)ao, aoh, aol, n8x, 1.f);

    // output projection
    gemm_mma<<<dim3(S_LEN / 128, 12), 256, GEMM_SMEM>>>(
        aoh, aol, oh, ol, bo, bo, bo, out, out, out, DIM / 128);
}